// round 1
// baseline (speedup 1.0000x reference)
#include <cuda_runtime.h>
#include <math.h>

// ---------------------------------------------------------------------------
// Problem constants: D=512, H=8, hd=64. T is runtime (6144 for the fixed setup).
// ---------------------------------------------------------------------------
#define MAX_T 8192
#define MAX_TILES 1024

// Scratch (device globals; no allocation allowed)
__device__ float g_qk [MAX_T * 1024];  // [T, 1024]: q = [:,0:512], k = [:,512:1024]
__device__ float g_v  [MAX_T * 512];
__device__ float g_ctx[MAX_T * 512];
__device__ float g_tmp[MAX_T * 512];
__device__ float g_h1 [MAX_T * 512];
__device__ float g_mid[MAX_T * 2048];
__device__ int   g_tiles[MAX_TILES * 4]; // (qstart, qlen, kstart, klen)
__device__ int   g_meta[4];              // [0] = ntiles

// ---------------------------------------------------------------------------
// Tile table builder. Detects int32 vs int64 cumsum (little-endian: int64 has
// zero high words, and cum[1] > 0 always, so raw32[1]==0 <=> int64).
// ---------------------------------------------------------------------------
__global__ void build_tiles_kernel(const int* __restrict__ cum_raw, int T) {
    bool is64 = (cum_raw[1] == 0);
    int nt = 0;
    for (int s = 0; s < 256; ++s) {
        int start = is64 ? cum_raw[2 * s] : cum_raw[s];
        if (start >= T) break;
        int end = is64 ? cum_raw[2 * (s + 1)] : cum_raw[s + 1];
        int len = end - start;
        for (int q0 = 0; q0 < len && nt < MAX_TILES; q0 += 64) {
            g_tiles[nt * 4 + 0] = start + q0;
            g_tiles[nt * 4 + 1] = min(64, len - q0);
            g_tiles[nt * 4 + 2] = start;
            g_tiles[nt * 4 + 3] = len;
            ++nt;
        }
        if (end >= T) break;
    }
    g_meta[0] = nt;
}

// ---------------------------------------------------------------------------
// Tiled SGEMM: C[M,N] = A[M,K] @ B[K,N] + bias[N]  (+ epilogue)
// EPI: 0 = bias; 1 = bias + exact GELU; 2 = bias + residual add
// BM=BN=128, BK=16, 256 threads, 8x8 per-thread micro-tile.
// Requires N % 128 == 0, K % 16 == 0 (true here: N in {512,1024,2048}).
// ---------------------------------------------------------------------------
template <int EPI>
__global__ void __launch_bounds__(256)
gemm128_kernel(const float* __restrict__ A, const float* __restrict__ B,
               const float* __restrict__ bias, const float* __restrict__ res,
               float* __restrict__ C, int M, int N, int K) {
    __shared__ float As[16][128];
    __shared__ float Bs[16][128];

    const int tid = threadIdx.x;
    const int tx  = tid & 15;
    const int ty  = tid >> 4;
    const int bm  = blockIdx.y * 128;
    const int bn  = blockIdx.x * 128;

    float acc[8][8];
#pragma unroll
    for (int i = 0; i < 8; ++i)
#pragma unroll
        for (int j = 0; j < 8; ++j) acc[i][j] = 0.f;

    for (int k0 = 0; k0 < K; k0 += 16) {
        // Load A tile (128x16), store transposed As[k][m]
#pragma unroll
        for (int p = 0; p < 2; ++p) {
            int l4  = tid + p * 256;      // 0..511 float4 slots
            int row = l4 >> 2;            // 0..127
            int kc  = (l4 & 3) * 4;       // 0,4,8,12
            float4 v = make_float4(0.f, 0.f, 0.f, 0.f);
            int gr = bm + row;
            if (gr < M) v = *(const float4*)(A + (size_t)gr * K + k0 + kc);
            As[kc + 0][row] = v.x;
            As[kc + 1][row] = v.y;
            As[kc + 2][row] = v.z;
            As[kc + 3][row] = v.w;
        }
        // Load B tile (16x128) directly
#pragma unroll
        for (int p = 0; p < 2; ++p) {
            int l4 = tid + p * 256;
            int kr = l4 >> 5;             // 0..15
            int nc = (l4 & 31) * 4;       // 0..124
            float4 v = *(const float4*)(B + (size_t)(k0 + kr) * N + bn + nc);
            *(float4*)&Bs[kr][nc] = v;
        }
        __syncthreads();

#pragma unroll
        for (int k = 0; k < 16; ++k) {
            float a[8], bb[8];
            *(float4*)(a)      = *(const float4*)&As[k][ty * 8];
            *(float4*)(a + 4)  = *(const float4*)&As[k][ty * 8 + 4];
            *(float4*)(bb)     = *(const float4*)&Bs[k][tx * 8];
            *(float4*)(bb + 4) = *(const float4*)&Bs[k][tx * 8 + 4];
#pragma unroll
            for (int i = 0; i < 8; ++i)
#pragma unroll
                for (int j = 0; j < 8; ++j) acc[i][j] += a[i] * bb[j];
        }
        __syncthreads();
    }

    // Epilogue
#pragma unroll
    for (int i = 0; i < 8; ++i) {
        int gr = bm + ty * 8 + i;
        if (gr >= M) continue;
#pragma unroll
        for (int j = 0; j < 8; ++j) {
            int gc = bn + tx * 8 + j;
            float c = acc[i][j] + bias[gc];
            if (EPI == 1) {
                c = 0.5f * c * (1.0f + erff(c * 0.70710678118654752f));
            } else if (EPI == 2) {
                c += res[(size_t)gr * N + gc];
            }
            C[(size_t)gr * N + gc] = c;
        }
    }
}

// ---------------------------------------------------------------------------
// Flash-style attention. One block = (one q-tile of <=64 rows, one head).
// QT=64, KT=32, hd=64. 256 threads as 16x16; thread owns 4 q-rows x 4 d-cols
// of O, and 4x2 of each S tile. Online softmax; row reductions across the
// 16 tx lanes via shfl_xor (half-warp safe: masks 1,2,4,8).
// ---------------------------------------------------------------------------
__global__ void __launch_bounds__(256)
attn_kernel(const float* __restrict__ qk, const float* __restrict__ v,
            float* __restrict__ ctx) {
    const int tile = blockIdx.x;
    if (tile >= g_meta[0]) return;
    const int h = blockIdx.y;

    const int qstart = g_tiles[tile * 4 + 0];
    const int qlen   = g_tiles[tile * 4 + 1];
    const int kstart = g_tiles[tile * 4 + 2];
    const int klen   = g_tiles[tile * 4 + 3];

    __shared__ float Qs[64][64];
    __shared__ float Ks[32][65];
    __shared__ float Vs[32][64];
    __shared__ float Ps[64][33];

    const int tid = threadIdx.x;
    const int tx  = tid & 15;
    const int ty  = tid >> 4;
    const int r0  = ty * 4;
    const int c0  = tx * 2;

    // Load Q tile (rows beyond qlen zeroed)
#pragma unroll
    for (int p = 0; p < 4; ++p) {
        int l4 = tid + p * 256;       // 0..1023
        int r  = l4 >> 4;             // 0..63
        int dc = (l4 & 15) * 4;       // 0..60
        float4 qv = make_float4(0.f, 0.f, 0.f, 0.f);
        if (r < qlen)
            qv = *(const float4*)(qk + (size_t)(qstart + r) * 1024 + h * 64 + dc);
        *(float4*)&Qs[r][dc] = qv;
    }

    float o[4][4];
    float m[4], l[4];
#pragma unroll
    for (int i = 0; i < 4; ++i) {
        m[i] = -1e30f; l[i] = 0.f;
#pragma unroll
        for (int j = 0; j < 4; ++j) o[i][j] = 0.f;
    }

    for (int kb = 0; kb < klen; kb += 32) {
        const int kn = min(32, klen - kb);
        // Load K,V blocks (32x64 each)
#pragma unroll
        for (int p = 0; p < 2; ++p) {
            int l4 = tid + p * 256;   // 0..511
            int r  = l4 >> 4;         // 0..31
            int dc = (l4 & 15) * 4;
            float4 kv = make_float4(0.f, 0.f, 0.f, 0.f);
            float4 vv = make_float4(0.f, 0.f, 0.f, 0.f);
            if (r < kn) {
                size_t t = (size_t)(kstart + kb + r);
                kv = *(const float4*)(qk + t * 1024 + 512 + h * 64 + dc);
                vv = *(const float4*)(v  + t * 512 + h * 64 + dc);
            }
            Ks[r][dc + 0] = kv.x; Ks[r][dc + 1] = kv.y;
            Ks[r][dc + 2] = kv.z; Ks[r][dc + 3] = kv.w;
            *(float4*)&Vs[r][dc] = vv;
        }
        __syncthreads();

        // S = Q @ K^T  (per thread: 4 rows x 2 keys)
        float s[4][2];
#pragma unroll
        for (int i = 0; i < 4; ++i) { s[i][0] = 0.f; s[i][1] = 0.f; }
#pragma unroll
        for (int d = 0; d < 64; d += 4) {
            float qv[4][4];
#pragma unroll
            for (int i = 0; i < 4; ++i)
                *(float4*)qv[i] = *(const float4*)&Qs[r0 + i][d];
            float k0v[4], k1v[4];
#pragma unroll
            for (int dd = 0; dd < 4; ++dd) {
                k0v[dd] = Ks[c0 + 0][d + dd];
                k1v[dd] = Ks[c0 + 1][d + dd];
            }
#pragma unroll
            for (int dd = 0; dd < 4; ++dd)
#pragma unroll
                for (int i = 0; i < 4; ++i) {
                    s[i][0] += qv[i][dd] * k0v[dd];
                    s[i][1] += qv[i][dd] * k1v[dd];
                }
        }

        // Online softmax per row
#pragma unroll
        for (int i = 0; i < 4; ++i) {
            float s0 = s[i][0] * 0.125f;
            float s1 = s[i][1] * 0.125f;
            if (kb + c0 + 0 >= klen) s0 = -1e30f;
            if (kb + c0 + 1 >= klen) s1 = -1e30f;
            float mb = fmaxf(s0, s1);
#pragma unroll
            for (int off = 8; off; off >>= 1)
                mb = fmaxf(mb, __shfl_xor_sync(0xffffffffu, mb, off));
            float mnew  = fmaxf(m[i], mb);
            float alpha = __expf(m[i] - mnew);
            float p0 = __expf(s0 - mnew);
            float p1 = __expf(s1 - mnew);
            float lb = p0 + p1;
#pragma unroll
            for (int off = 8; off; off >>= 1)
                lb += __shfl_xor_sync(0xffffffffu, lb, off);
            l[i] = l[i] * alpha + lb;
            m[i] = mnew;
#pragma unroll
            for (int j = 0; j < 4; ++j) o[i][j] *= alpha;
            Ps[r0 + i][c0 + 0] = p0;
            Ps[r0 + i][c0 + 1] = p1;
        }
        __syncthreads();

        // O += P @ V  (per thread: 4 rows x 4 d-cols)
#pragma unroll
        for (int k = 0; k < 32; ++k) {
            float4 vv = *(const float4*)&Vs[k][tx * 4];
            float p0 = Ps[r0 + 0][k];
            float p1 = Ps[r0 + 1][k];
            float p2 = Ps[r0 + 2][k];
            float p3 = Ps[r0 + 3][k];
            o[0][0] += p0 * vv.x; o[0][1] += p0 * vv.y; o[0][2] += p0 * vv.z; o[0][3] += p0 * vv.w;
            o[1][0] += p1 * vv.x; o[1][1] += p1 * vv.y; o[1][2] += p1 * vv.z; o[1][3] += p1 * vv.w;
            o[2][0] += p2 * vv.x; o[2][1] += p2 * vv.y; o[2][2] += p2 * vv.z; o[2][3] += p2 * vv.w;
            o[3][0] += p3 * vv.x; o[3][1] += p3 * vv.y; o[3][2] += p3 * vv.z; o[3][3] += p3 * vv.w;
        }
        __syncthreads();
    }

    // Write ctx (only valid query rows)
#pragma unroll
    for (int i = 0; i < 4; ++i) {
        int r = r0 + i;
        if (r < qlen) {
            float inv = 1.0f / l[i];
            float4 out = make_float4(o[i][0] * inv, o[i][1] * inv,
                                     o[i][2] * inv, o[i][3] * inv);
            *(float4*)(ctx + (size_t)(qstart + r) * 512 + h * 64 + tx * 4) = out;
        }
    }
}

// ---------------------------------------------------------------------------
// Row-wise LayerNorm over D=512. One block per row, 256 threads.
// ---------------------------------------------------------------------------
__global__ void __launch_bounds__(256)
ln_kernel(const float* __restrict__ x, const float* __restrict__ g,
          const float* __restrict__ b, float* __restrict__ y) {
    const int row = blockIdx.x;
    const int tid = threadIdx.x;
    const float* xr = x + (size_t)row * 512;
    float v0 = xr[tid], v1 = xr[tid + 256];
    float s = v0 + v1;
    float q = v0 * v0 + v1 * v1;
#pragma unroll
    for (int off = 16; off; off >>= 1) {
        s += __shfl_xor_sync(0xffffffffu, s, off);
        q += __shfl_xor_sync(0xffffffffu, q, off);
    }
    __shared__ float ss[8], sq[8];
    int w = tid >> 5;
    if ((tid & 31) == 0) { ss[w] = s; sq[w] = q; }
    __syncthreads();
    if (tid < 32) {
        float s2 = (tid < 8) ? ss[tid] : 0.f;
        float q2 = (tid < 8) ? sq[tid] : 0.f;
#pragma unroll
        for (int off = 4; off; off >>= 1) {
            s2 += __shfl_xor_sync(0xffffffffu, s2, off);
            q2 += __shfl_xor_sync(0xffffffffu, q2, off);
        }
        if (tid == 0) { ss[0] = s2; sq[0] = q2; }
    }
    __syncthreads();
    float mean = ss[0] * (1.0f / 512.0f);
    float var  = sq[0] * (1.0f / 512.0f) - mean * mean;
    float rstd = rsqrtf(var + 1e-5f);
    y[(size_t)row * 512 + tid]       = (v0 - mean) * rstd * g[tid]       + b[tid];
    y[(size_t)row * 512 + tid + 256] = (v1 - mean) * rstd * g[tid + 256] + b[tid + 256];
}

// ---------------------------------------------------------------------------
// Launch
// ---------------------------------------------------------------------------
extern "C" void kernel_launch(void* const* d_in, const int* in_sizes, int n_in,
                              void* d_out, int out_size) {
    const float* h_n     = (const float*)d_in[0];
    const float* to_v_w  = (const float*)d_in[1];
    const float* to_v_b  = (const float*)d_in[2];
    const float* to_qk_w = (const float*)d_in[3];
    const float* to_qk_b = (const float*)d_in[4];
    const float* proj_w  = (const float*)d_in[5];
    const float* proj_b  = (const float*)d_in[6];
    const float* ffn_w1  = (const float*)d_in[7];
    const float* ffn_b1  = (const float*)d_in[8];
    const float* ffn_w2  = (const float*)d_in[9];
    const float* ffn_b2  = (const float*)d_in[10];
    const float* ln1_g   = (const float*)d_in[11];
    const float* ln1_b   = (const float*)d_in[12];
    const float* ln2_g   = (const float*)d_in[13];
    const float* ln2_b   = (const float*)d_in[14];
    const int*   cum     = (const int*)d_in[15];

    const int T = in_sizes[0] / 512;
    if (T <= 0 || T > MAX_T) return;

    float *qk, *v, *ctx, *tmp, *h1, *mid;
    cudaGetSymbolAddress((void**)&qk,  g_qk);
    cudaGetSymbolAddress((void**)&v,   g_v);
    cudaGetSymbolAddress((void**)&ctx, g_ctx);
    cudaGetSymbolAddress((void**)&tmp, g_tmp);
    cudaGetSymbolAddress((void**)&h1,  g_h1);
    cudaGetSymbolAddress((void**)&mid, g_mid);

    const int MB = (T + 127) / 128;

    // 0) tile table for ragged attention
    build_tiles_kernel<<<1, 1>>>(cum, T);

    // 1) v = h_n @ to_v_w + b ; qk = h_n @ to_qk_w + b
    gemm128_kernel<0><<<dim3(512 / 128, MB), 256>>>(h_n, to_v_w, to_v_b, nullptr, v, T, 512, 512);
    gemm128_kernel<0><<<dim3(1024 / 128, MB), 256>>>(h_n, to_qk_w, to_qk_b, nullptr, qk, T, 1024, 512);

    // 2) attention
    {
        int gx = (T + 63) / 64 + 64;  // upper bound incl. boundary fragmentation
        attn_kernel<<<dim3(gx, 8), 256>>>(qk, v, ctx);
    }

    // 3) tmp = h_n + ctx @ proj_w + proj_b ; h1 = LN1(tmp)
    gemm128_kernel<2><<<dim3(512 / 128, MB), 256>>>(ctx, proj_w, proj_b, h_n, tmp, T, 512, 512);
    ln_kernel<<<T, 256>>>(tmp, ln1_g, ln1_b, h1);

    // 4) mid = gelu(h1 @ ffn_w1 + b1)
    gemm128_kernel<1><<<dim3(2048 / 128, MB), 256>>>(h1, ffn_w1, ffn_b1, nullptr, mid, T, 2048, 512);

    // 5) tmp = h1 + mid @ ffn_w2 + b2 ; out = LN2(tmp)
    gemm128_kernel<2><<<dim3(512 / 128, MB), 256>>>(mid, ffn_w2, ffn_b2, h1, tmp, T, 512, 2048);
    ln_kernel<<<T, 256>>>(tmp, ln2_g, ln2_b, (float*)d_out);
}